// round 8
// baseline (speedup 1.0000x reference)
#include <cuda_runtime.h>
#include <cuda_bf16.h>
#include <cstring>
#include <cstdint>

// ---------------------------------------------------------------------------
// HyperEConv, HMMA bf16-split GEMMs, restructured dependence graph:
//   B: CSR-x (histx,offx,placex) ; then CSR-w (histw,offw,placew)
//   A: conv_w ; wv = w@Ww1^T+bw1 ; [wait sr1a] xv-with-mul -> out_x
//   C: we = w@Ww2^T+bw2
//   0: sr1a: aggr = segsum_v(wv[eidx])        (gather-reduce)
//      final: w_new = we*(1 + gather_gemm)    (fused sr2 + GEMM)
// GEMM: D = Ahi*Bhi + Ahi*Blo + Alo*Bhi  (bf16 in, fp32 accum)
// Output: [w_new (N_W*128) | x_new (N_X*128)]  float32
// ---------------------------------------------------------------------------

#define MAX_NX 100000
#define MAX_NW 25000
#define MAX_E  800000
#define D 128

__device__ float g_aggr[MAX_NX * D];
__device__ float g_wv  [MAX_NW * D];
__device__ float g_we  [MAX_NW * D];

// precomputed bf16 weights: [mat][hi=0/lo=1][2048 uint4] swizzled
__device__ uint4 g_wbf[4][2][2048];

// counts: x segs [0,NX), w segs [NX,NX+NW), 2 counters after that.
// INVARIANT: region [0, NX+NW+2) all-zero at entry of every run.
__device__ int g_cnt [MAX_NX + MAX_NW + 2];
__device__ int g_beg [MAX_NX + MAX_NW];
__device__ int g_cur [MAX_NX + MAX_NW];
__device__ int g_srcx[MAX_E];
__device__ int g_srcw[MAX_E];

__device__ __forceinline__ uint32_t smem_u32(const void* p) {
    uint32_t a;
    asm("{ .reg .u64 t; cvta.to.shared.u64 t, %1; cvt.u32.u64 %0, t; }"
        : "=r"(a) : "l"(p));
    return a;
}

__device__ __forceinline__ void ldmx4(uint32_t* r, uint32_t addr) {
    asm volatile("ldmatrix.sync.aligned.m8n8.x4.shared.b16 {%0,%1,%2,%3}, [%4];"
                 : "=r"(r[0]), "=r"(r[1]), "=r"(r[2]), "=r"(r[3]) : "r"(addr));
}

__device__ __forceinline__ void mma_bf16(float* d, const uint32_t* a,
                                         uint32_t b0, uint32_t b1) {
    asm volatile(
        "mma.sync.aligned.m16n8k16.row.col.f32.bf16.bf16.f32 "
        "{%0,%1,%2,%3}, {%4,%5,%6,%7}, {%8,%9}, {%0,%1,%2,%3};"
        : "+f"(d[0]), "+f"(d[1]), "+f"(d[2]), "+f"(d[3])
        : "r"(a[0]), "r"(a[1]), "r"(a[2]), "r"(a[3]), "r"(b0), "r"(b1));
}

__device__ __forceinline__ void split2(float f0, float f1, uint32_t& hi, uint32_t& lo) {
    __nv_bfloat162 hh = __floats2bfloat162_rn(f0, f1);
    float r0 = f0 - __bfloat162float(hh.x);
    float r1 = f1 - __bfloat162float(hh.y);
    __nv_bfloat162 ll = __floats2bfloat162_rn(r0, r1);
    memcpy(&hi, &hh, 4);
    memcpy(&lo, &ll, 4);
}

#define SM_AHI  0
#define SM_ALO  16384
#define SM_BHI  32768
#define SM_BLO  65536
#define SM_TOT  98304

extern __shared__ char smc[];

// ---------------------------------------------------------------------------
// Weight precompute: 4 [128x128] fp32 -> swizzled bf16 hi/lo
// ---------------------------------------------------------------------------
__global__ void conv_w_kernel(const float* __restrict__ W0, const float* __restrict__ W1,
                              const float* __restrict__ W2, const float* __restrict__ W3)
{
    const int t = blockIdx.x * blockDim.x + threadIdx.x;
    if (t >= 8192) return;
    const int mat = t >> 11;
    const int rem = t & 2047;
    const int r = rem >> 4;
    const int c = rem & 15;
    const float* Wm = (mat == 0) ? W0 : (mat == 1) ? W1 : (mat == 2) ? W2 : W3;
    const float4 u = *(const float4*)(Wm + r * 128 + c * 8);
    const float4 v = *(const float4*)(Wm + r * 128 + c * 8 + 4);
    uint4 hi, lo;
    split2(u.x, u.y, hi.x, lo.x);
    split2(u.z, u.w, hi.y, lo.y);
    split2(v.x, v.y, hi.z, lo.z);
    split2(v.z, v.w, hi.w, lo.w);
    const int off = r * 16 + (c ^ (r & 7));
    g_wbf[mat][0][off] = hi;
    g_wbf[mat][1][off] = lo;
}

// ---------------------------------------------------------------------------
// shared GEMM core pieces
// ---------------------------------------------------------------------------
__device__ __forceinline__ void load_weights_smem(int wmat, int tid) {
    const uint4* whi = g_wbf[wmat][0];
    const uint4* wlo = g_wbf[wmat][1];
    uint4* shi = (uint4*)(smc + SM_BHI);
    uint4* slo = (uint4*)(smc + SM_BLO);
    #pragma unroll
    for (int it = 0; it < 8; it++) {
        const int i = tid + it * 256;
        shi[i] = whi[i];
        slo[i] = wlo[i];
    }
}

// mainloop: warps 2(m) x 4(n); acc[2][4][4]
__device__ __forceinline__ void mma_mainloop(uint32_t sb, int tid, float acc[2][4][4]) {
    const int lane = tid & 31;
    const int wid  = tid >> 5;
    const int m0 = (wid & 1) * 32;
    const int n0 = (wid >> 1) * 32;
    const int sub = lane >> 3, l8 = lane & 7;
    for (int ks = 0; ks < 8; ks++) {
        uint32_t ahi[2][4], alo[2][4], bhi[2][4], blo[2][4];
        #pragma unroll
        for (int at = 0; at < 2; at++) {
            const int ar  = m0 + at * 16 + (sub & 1) * 8 + l8;
            const int akc = ks * 2 + (sub >> 1);
            const uint32_t aoff = (uint32_t)ar * 256u + (uint32_t)((akc ^ (ar & 7)) << 4);
            ldmx4(ahi[at], sb + SM_AHI + aoff);
            ldmx4(alo[at], sb + SM_ALO + aoff);
        }
        #pragma unroll
        for (int bp = 0; bp < 2; bp++) {
            const int br  = n0 + bp * 16 + (sub >> 1) * 8 + l8;
            const int bkc = ks * 2 + (sub & 1);
            const uint32_t boff = (uint32_t)br * 256u + (uint32_t)((bkc ^ (br & 7)) << 4);
            ldmx4(bhi[bp], sb + SM_BHI + boff);
            ldmx4(blo[bp], sb + SM_BLO + boff);
        }
        #pragma unroll
        for (int at = 0; at < 2; at++) {
            #pragma unroll
            for (int nt = 0; nt < 4; nt++) {
                const int bp = nt >> 1, o = (nt & 1) * 2;
                mma_bf16(acc[at][nt], ahi[at], bhi[bp][o], bhi[bp][o + 1]);
                mma_bf16(acc[at][nt], ahi[at], blo[bp][o], blo[bp][o + 1]);
                mma_bf16(acc[at][nt], alo[at], bhi[bp][o], bhi[bp][o + 1]);
            }
        }
    }
}

// ---------------------------------------------------------------------------
// Plain HMMA GEMM.
//   v = A@W^T + bias
//   mode 0: out = v
//   mode 2: out = v*(1+mul[row])   (elementwise, mul fp32 [M,128])
// ---------------------------------------------------------------------------
__global__ void __launch_bounds__(256, 2)
gemm_hmma_kernel(const float* __restrict__ A, int wmat,
                 const float* __restrict__ bias, float* __restrict__ C, int M,
                 const float* __restrict__ mulSrc, int mode)
{
    const uint32_t sb = smem_u32(smc);
    const int tid = threadIdx.x;
    const int rowBase = blockIdx.x * 64;

    load_weights_smem(wmat, tid);

    // convert A tile (64 rows) to bf16 hi/lo swizzled smem
    #pragma unroll
    for (int it = 0; it < 4; it++) {
        const int task = tid + it * 256;     // 0..1023
        const int r = task >> 4;
        const int c = task & 15;
        const int grow = rowBase + r;
        float4 u = make_float4(0.f, 0.f, 0.f, 0.f), v = u;
        if (grow < M) {
            const float* Ar = A + (size_t)grow * D + c * 8;
            u = *(const float4*)Ar;
            v = *(const float4*)(Ar + 4);
        }
        uint4 hi, lo;
        split2(u.x, u.y, hi.x, lo.x);
        split2(u.z, u.w, hi.y, lo.y);
        split2(v.x, v.y, hi.z, lo.z);
        split2(v.z, v.w, hi.w, lo.w);
        const uint32_t off = (uint32_t)r * 256u + (uint32_t)((c ^ (r & 7)) << 4);
        *(uint4*)(smc + SM_AHI + off) = hi;
        *(uint4*)(smc + SM_ALO + off) = lo;
    }
    __syncthreads();

    float acc[2][4][4];
    #pragma unroll
    for (int at = 0; at < 2; at++)
        #pragma unroll
        for (int nt = 0; nt < 4; nt++)
            #pragma unroll
            for (int q = 0; q < 4; q++) acc[at][nt][q] = 0.f;

    mma_mainloop(sb, tid, acc);

    // epilogue
    const int lane = tid & 31;
    const int wid  = tid >> 5;
    const int m0 = (wid & 1) * 32;
    const int n0 = (wid >> 1) * 32;
    #pragma unroll
    for (int at = 0; at < 2; at++) {
        const int rA = rowBase + m0 + at * 16 + (lane >> 2);
        const int rB = rA + 8;
        #pragma unroll
        for (int nt = 0; nt < 4; nt++) {
            const int col = n0 + nt * 8 + (lane & 3) * 2;
            const float2 b2 = *(const float2*)(bias + col);
            if (rA < M) {
                float v0 = acc[at][nt][0] + b2.x;
                float v1 = acc[at][nt][1] + b2.y;
                if (mode == 2) {
                    float2 m = *(const float2*)(mulSrc + (size_t)rA * D + col);
                    v0 = fmaf(v0, m.x, v0);
                    v1 = fmaf(v1, m.y, v1);
                }
                *(float2*)(C + (size_t)rA * D + col) = make_float2(v0, v1);
            }
            if (rB < M) {
                float v0 = acc[at][nt][2] + b2.x;
                float v1 = acc[at][nt][3] + b2.y;
                if (mode == 2) {
                    float2 m = *(const float2*)(mulSrc + (size_t)rB * D + col);
                    v0 = fmaf(v0, m.x, v0);
                    v1 = fmaf(v1, m.y, v1);
                }
                *(float2*)(C + (size_t)rB * D + col) = make_float2(v0, v1);
            }
        }
    }
}

// ---------------------------------------------------------------------------
// Fused gather + GEMM (final step):
//   s[r] = segsum over CSR-w of src rows; v = s@W^T + bias*deg
//   out  = mul*(1+v)        (mul = we)
// ---------------------------------------------------------------------------
__global__ void __launch_bounds__(256, 2)
gemm_gather_kernel(const int* __restrict__ beg, const int* __restrict__ cnt,
                   const int* __restrict__ lst, const float* __restrict__ src,
                   int wmat, const float* __restrict__ bias,
                   const float* __restrict__ mulSrc, float* __restrict__ C, int M)
{
    const uint32_t sb = smem_u32(smc);
    const int tid = threadIdx.x;
    const int lane = tid & 31;
    const int wid  = tid >> 5;
    const int rowBase = blockIdx.x * 64;

    load_weights_smem(wmat, tid);

    // gather-reduce 8 segments per warp directly into bf16 hi/lo smem
    const int j = lane * 4;
    #pragma unroll 1
    for (int i = 0; i < 8; i++) {
        const int r = wid * 8 + i;
        const int seg = rowBase + r;
        float4 acc = make_float4(0.f, 0.f, 0.f, 0.f);
        if (seg < M) {
            int k = beg[seg];
            const int end = k + cnt[seg];
            for (; k + 8 <= end; k += 8) {
                int si[8];
                #pragma unroll
                for (int q = 0; q < 8; q++) si[q] = __ldg(&lst[k + q]);
                float4 v[8];
                #pragma unroll
                for (int q = 0; q < 8; q++)
                    v[q] = *(const float4*)(src + (size_t)si[q] * D + j);
                #pragma unroll
                for (int q = 0; q < 8; q++) {
                    acc.x += v[q].x; acc.y += v[q].y; acc.z += v[q].z; acc.w += v[q].w;
                }
            }
            if (k < end) {   // predicated batch tail
                int si[8];
                #pragma unroll
                for (int q = 0; q < 8; q++) {
                    int kk = (k + q < end) ? (k + q) : (end - 1);
                    si[q] = __ldg(&lst[kk]);
                }
                float4 v[8];
                #pragma unroll
                for (int q = 0; q < 8; q++)
                    v[q] = *(const float4*)(src + (size_t)si[q] * D + j);
                #pragma unroll
                for (int q = 0; q < 8; q++) {
                    if (k + q < end) {
                        acc.x += v[q].x; acc.y += v[q].y;
                        acc.z += v[q].z; acc.w += v[q].w;
                    }
                }
            }
        }
        uint32_t h0, l0, h1, l1;
        split2(acc.x, acc.y, h0, l0);
        split2(acc.z, acc.w, h1, l1);
        const int c = lane >> 1;
        const uint32_t off = (uint32_t)r * 256u +
                             (uint32_t)((c ^ (r & 7)) << 4) + (uint32_t)(lane & 1) * 8;
        *(uint2*)(smc + SM_AHI + off) = make_uint2(h0, h1);
        *(uint2*)(smc + SM_ALO + off) = make_uint2(l0, l1);
    }
    __syncthreads();

    float acc[2][4][4];
    #pragma unroll
    for (int at = 0; at < 2; at++)
        #pragma unroll
        for (int nt = 0; nt < 4; nt++)
            #pragma unroll
            for (int q = 0; q < 4; q++) acc[at][nt][q] = 0.f;

    mma_mainloop(sb, tid, acc);

    // epilogue: v = acc + bias*deg ; out = m*(1+v)
    const int m0 = (wid & 1) * 32;
    const int n0 = (wid >> 1) * 32;
    #pragma unroll
    for (int at = 0; at < 2; at++) {
        const int rA = rowBase + m0 + at * 16 + (lane >> 2);
        const int rB = rA + 8;
        float dA = 0.f, dB = 0.f;
        if (rA < M) dA = (float)cnt[rA];
        if (rB < M) dB = (float)cnt[rB];
        #pragma unroll
        for (int nt = 0; nt < 4; nt++) {
            const int col = n0 + nt * 8 + (lane & 3) * 2;
            const float2 b2 = *(const float2*)(bias + col);
            if (rA < M) {
                float v0 = acc[at][nt][0] + b2.x * dA;
                float v1 = acc[at][nt][1] + b2.y * dA;
                float2 m = *(const float2*)(mulSrc + (size_t)rA * D + col);
                v0 = fmaf(m.x, v0, m.x);
                v1 = fmaf(m.y, v1, m.y);
                *(float2*)(C + (size_t)rA * D + col) = make_float2(v0, v1);
            }
            if (rB < M) {
                float v0 = acc[at][nt][2] + b2.x * dB;
                float v1 = acc[at][nt][3] + b2.y * dB;
                float2 m = *(const float2*)(mulSrc + (size_t)rB * D + col);
                v0 = fmaf(m.x, v0, m.x);
                v1 = fmaf(m.y, v1, m.y);
                *(float2*)(C + (size_t)rB * D + col) = make_float2(v0, v1);
            }
        }
    }
}

// ---------------------------------------------------------------------------
// CSR build (one direction at a time)
// ---------------------------------------------------------------------------
__global__ void hist1_kernel(const int* __restrict__ idx, int* __restrict__ cnt, int E)
{
    int e = blockIdx.x * blockDim.x + threadIdx.x;
    if (e < E) atomicAdd(&cnt[idx[e]], 1);
}

__global__ void __launch_bounds__(1024)
offsets1_kernel(const int* __restrict__ cnt, int* __restrict__ beg,
                int* __restrict__ cur, int* __restrict__ ctr, int n)
{
    const int t = threadIdx.x;
    const int i = blockIdx.x * 1024 + t;
    int v = (i < n) ? cnt[i] : 0;

    const int lane = t & 31, wd = t >> 5;
    int s = v;
    #pragma unroll
    for (int o = 1; o < 32; o <<= 1) {
        int u = __shfl_up_sync(0xffffffffu, s, o);
        if (lane >= o) s += u;
    }
    __shared__ int wsum[32];
    __shared__ int base;
    if (lane == 31) wsum[wd] = s;
    __syncthreads();
    if (wd == 0) {
        int ws = wsum[lane];
        #pragma unroll
        for (int o = 1; o < 32; o <<= 1) {
            int u = __shfl_up_sync(0xffffffffu, ws, o);
            if (lane >= o) ws += u;
        }
        wsum[lane] = ws;
        if (lane == 31) base = atomicAdd(ctr, ws);
    }
    __syncthreads();
    int excl = base + s - v + (wd > 0 ? wsum[wd - 1] : 0);
    if (i < n) { beg[i] = excl; cur[i] = excl; }
}

__global__ void place1_kernel(const int* __restrict__ key, const int* __restrict__ val,
                              int* __restrict__ cur, int* __restrict__ dst, int E)
{
    int e = blockIdx.x * blockDim.x + threadIdx.x;
    if (e < E) {
        int p = atomicAdd(&cur[key[e]], 1);
        dst[p] = val[e];
    }
}

__global__ void zero_kernel(int* __restrict__ p, int n)
{
    int i = blockIdx.x * blockDim.x + threadIdx.x;
    if (i < n) p[i] = 0;
}

// ---------------------------------------------------------------------------
// Segment gather-reduce (aggr only): warp per segment, predicated 8-wide tail
// ---------------------------------------------------------------------------
__global__ void seg_reduce_kernel(const int* __restrict__ beg, const int* __restrict__ cnt,
                                  const int* __restrict__ lst,
                                  const float* __restrict__ src,
                                  float* __restrict__ out, int N)
{
    const int seg  = (blockIdx.x * blockDim.x + threadIdx.x) >> 5;
    const int lane = threadIdx.x & 31;
    if (seg >= N) return;
    int k = beg[seg];
    const int end = k + cnt[seg];
    const int j = lane * 4;
    float4 acc = make_float4(0.f, 0.f, 0.f, 0.f);

    for (; k + 8 <= end; k += 8) {
        int si[8];
        #pragma unroll
        for (int q = 0; q < 8; q++) si[q] = __ldg(&lst[k + q]);
        float4 v[8];
        #pragma unroll
        for (int q = 0; q < 8; q++)
            v[q] = *(const float4*)(src + (size_t)si[q] * D + j);
        #pragma unroll
        for (int q = 0; q < 8; q++) {
            acc.x += v[q].x; acc.y += v[q].y; acc.z += v[q].z; acc.w += v[q].w;
        }
    }
    if (k < end) {
        int si[8];
        #pragma unroll
        for (int q = 0; q < 8; q++) {
            int kk = (k + q < end) ? (k + q) : (end - 1);
            si[q] = __ldg(&lst[kk]);
        }
        float4 v[8];
        #pragma unroll
        for (int q = 0; q < 8; q++)
            v[q] = *(const float4*)(src + (size_t)si[q] * D + j);
        #pragma unroll
        for (int q = 0; q < 8; q++) {
            if (k + q < end) {
                acc.x += v[q].x; acc.y += v[q].y; acc.z += v[q].z; acc.w += v[q].w;
            }
        }
    }
    *(float4*)(out + (size_t)seg * D + j) = acc;
}

extern "C" void kernel_launch(void* const* d_in, const int* in_sizes, int n_in,
                              void* d_out, int out_size)
{
    const float* x   = (const float*)d_in[0];
    const float* w   = (const float*)d_in[1];
    const float* Wx1 = (const float*)d_in[2];
    const float* bx1 = (const float*)d_in[3];
    const float* Ww1 = (const float*)d_in[4];
    const float* bw1 = (const float*)d_in[5];
    const float* Wx2 = (const float*)d_in[6];
    const float* bx2 = (const float*)d_in[7];
    const float* Ww2 = (const float*)d_in[8];
    const float* bw2 = (const float*)d_in[9];
    const int*   h   = (const int*)d_in[10];

    const int N_X = in_sizes[0] / D;
    const int N_W = in_sizes[1] / D;
    const int E   = in_sizes[10] / 2;
    const int* vidx = h;
    const int* eidx = h + E;

    float* out_w = (float*)d_out;
    float* out_x = (float*)d_out + (size_t)N_W * D;

    float *p_aggr, *p_wv, *p_we;
    int *p_cnt, *p_beg, *p_cur, *p_srcx, *p_srcw;
    cudaGetSymbolAddress((void**)&p_aggr, g_aggr);
    cudaGetSymbolAddress((void**)&p_wv,   g_wv);
    cudaGetSymbolAddress((void**)&p_we,   g_we);
    cudaGetSymbolAddress((void**)&p_cnt,  g_cnt);
    cudaGetSymbolAddress((void**)&p_beg,  g_beg);
    cudaGetSymbolAddress((void**)&p_cur,  g_cur);
    cudaGetSymbolAddress((void**)&p_srcx, g_srcx);
    cudaGetSymbolAddress((void**)&p_srcw, g_srcw);
    int* p_ctr = p_cnt + N_X + N_W;   // 2 counters right after used region

    cudaFuncSetAttribute(gemm_hmma_kernel,
                         cudaFuncAttributeMaxDynamicSharedMemorySize, SM_TOT);
    cudaFuncSetAttribute(gemm_gather_kernel,
                         cudaFuncAttributeMaxDynamicSharedMemorySize, SM_TOT);

    static cudaStream_t sA = nullptr, sB = nullptr, sC = nullptr;
    static cudaEvent_t e0, eBx, eWV, eS1a, eA2, eBw, eC;
    if (sA == nullptr) {
        cudaStreamCreateWithFlags(&sA, cudaStreamNonBlocking);
        cudaStreamCreateWithFlags(&sB, cudaStreamNonBlocking);
        cudaStreamCreateWithFlags(&sC, cudaStreamNonBlocking);
        cudaEventCreateWithFlags(&e0,   cudaEventDisableTiming);
        cudaEventCreateWithFlags(&eBx,  cudaEventDisableTiming);
        cudaEventCreateWithFlags(&eWV,  cudaEventDisableTiming);
        cudaEventCreateWithFlags(&eS1a, cudaEventDisableTiming);
        cudaEventCreateWithFlags(&eA2,  cudaEventDisableTiming);
        cudaEventCreateWithFlags(&eBw,  cudaEventDisableTiming);
        cudaEventCreateWithFlags(&eC,   cudaEventDisableTiming);
    }

    const int gx  = (N_X + 63) / 64;
    const int gw  = (N_W + 63) / 64;
    const int nbx = (N_X + 1023) / 1024;
    const int nbw = (N_W + 1023) / 1024;
    const int ge  = (E + 255) / 256;

    // fork
    cudaEventRecord(e0, 0);
    cudaStreamWaitEvent(sA, e0, 0);
    cudaStreamWaitEvent(sB, e0, 0);
    cudaStreamWaitEvent(sC, e0, 0);

    // ---- stream B: CSR-x (launches 1-3) ----
    hist1_kernel<<<ge, 256, 0, sB>>>(vidx, p_cnt, E);
    offsets1_kernel<<<nbx, 1024, 0, sB>>>(p_cnt, p_beg, p_cur, p_ctr, N_X);
    place1_kernel<<<ge, 256, 0, sB>>>(vidx, eidx, p_cur, p_srcx, E);
    cudaEventRecord(eBx, sB);

    // ---- stream A: conv_w + wv GEMM (launches 4-5) ----
    conv_w_kernel<<<32, 256, 0, sA>>>(Ww1, Wx1, Ww2, Wx2);
    gemm_hmma_kernel<<<gw, 256, SM_TOT, sA>>>(w, 0, bw1, p_wv, N_W, nullptr, 0);
    cudaEventRecord(eWV, sA);

    // ---- launch 6 (PROFILED): sr1a: aggr = segsum_v(wv) ----
    cudaStreamWaitEvent(0, eBx, 0);
    cudaStreamWaitEvent(0, eWV, 0);
    seg_reduce_kernel<<<(N_X + 7) / 8, 256>>>(p_beg, p_cnt, p_srcx, p_wv, p_aggr, N_X);
    cudaEventRecord(eS1a, 0);

    // ---- stream C: we GEMM (overlaps sr1a) ----
    cudaStreamWaitEvent(sC, eWV, 0);
    gemm_hmma_kernel<<<gw, 256, SM_TOT, sC>>>(w, 2, bw2, p_we, N_W, nullptr, 0);
    cudaEventRecord(eC, sC);

    // ---- stream A: xv GEMM with x_new fusion: out_x = v*(1+aggr) ----
    cudaStreamWaitEvent(sA, eS1a, 0);
    gemm_hmma_kernel<<<gx, 256, SM_TOT, sA>>>(x, 1, bx1, out_x, N_X, p_aggr, 2);
    cudaEventRecord(eA2, sA);

    // ---- stream B: CSR-w (overlaps sr1a + xv GEMM) ----
    hist1_kernel<<<ge, 256, 0, sB>>>(eidx, p_cnt + N_X, E);
    offsets1_kernel<<<nbw, 1024, 0, sB>>>(p_cnt + N_X, p_beg + N_X, p_cur + N_X,
                                          p_ctr + 1, N_W);
    place1_kernel<<<ge, 256, 0, sB>>>(eidx, vidx, p_cur + N_X, p_srcw, E);
    cudaEventRecord(eBw, sB);

    // ---- final: fused gather + GEMM: w_new = we*(1 + segsum(out_x)@Wx2^T + deg*bx2) ----
    cudaStreamWaitEvent(0, eA2, 0);
    cudaStreamWaitEvent(0, eBw, 0);
    cudaStreamWaitEvent(0, eC, 0);
    gemm_gather_kernel<<<gw, 256, SM_TOT>>>(p_beg + N_X, p_cnt + N_X, p_srcw,
                                            out_x, 3, bx2, p_we, out_w, N_W);

    // ---- tail: restore zero-invariant (cnt-x, cnt-w, counters) ----
    zero_kernel<<<(N_X + N_W + 2 + 255) / 256, 256>>>(p_cnt, N_X + N_W + 2);
}

// round 9
// speedup vs baseline: 1.2027x; 1.2027x over previous
#include <cuda_runtime.h>
#include <cuda_bf16.h>
#include <cstring>
#include <cstdint>

// ---------------------------------------------------------------------------
// HyperEConv, HMMA bf16-split GEMMs (round-7 structure + split CSR + pred tails)
//   B: CSR-x (histx,offx,placex) ; then CSR-w (histw,offw,placew)
//   A: conv_w ; wv = w@Ww1^T+bw1 ; xv = x@Wx1^T+bx1
//   C: we = w@Ww2^T+bw2
//   0: sr1: out_x = xv*(1 + segsum_v(wv[eidx]))     (waits CSR-x + A)
//      sr2: s = segsum_e(out_x[vidx])               (waits CSR-w)
//      final: w_new = we*(1 + s@Wx2^T + deg_w*bx2)
// GEMM: D = Ahi*Bhi + Ahi*Blo + Alo*Bhi  (bf16 in, fp32 accum)
// Output: [w_new (N_W*128) | x_new (N_X*128)]  float32
// ---------------------------------------------------------------------------

#define MAX_NX 100000
#define MAX_NW 25000
#define MAX_E  800000
#define D 128

__device__ float g_xv [MAX_NX * D];
__device__ float g_wv [MAX_NW * D];
__device__ float g_we [MAX_NW * D];
__device__ float g_s  [MAX_NW * D];

// precomputed bf16 weights: [mat][hi=0/lo=1][2048 uint4] swizzled
__device__ uint4 g_wbf[4][2][2048];

// counts: x segs [0,NX), w segs [NX,NX+NW), 2 counters after that.
// INVARIANT: region [0, NX+NW+2) all-zero at entry of every run.
__device__ int g_cnt [MAX_NX + MAX_NW + 2];
__device__ int g_beg [MAX_NX + MAX_NW];
__device__ int g_cur [MAX_NX + MAX_NW];
__device__ int g_srcx[MAX_E];
__device__ int g_srcw[MAX_E];

__device__ __forceinline__ uint32_t smem_u32(const void* p) {
    uint32_t a;
    asm("{ .reg .u64 t; cvta.to.shared.u64 t, %1; cvt.u32.u64 %0, t; }"
        : "=r"(a) : "l"(p));
    return a;
}

__device__ __forceinline__ void ldmx4(uint32_t* r, uint32_t addr) {
    asm volatile("ldmatrix.sync.aligned.m8n8.x4.shared.b16 {%0,%1,%2,%3}, [%4];"
                 : "=r"(r[0]), "=r"(r[1]), "=r"(r[2]), "=r"(r[3]) : "r"(addr));
}

__device__ __forceinline__ void mma_bf16(float* d, const uint32_t* a,
                                         uint32_t b0, uint32_t b1) {
    asm volatile(
        "mma.sync.aligned.m16n8k16.row.col.f32.bf16.bf16.f32 "
        "{%0,%1,%2,%3}, {%4,%5,%6,%7}, {%8,%9}, {%0,%1,%2,%3};"
        : "+f"(d[0]), "+f"(d[1]), "+f"(d[2]), "+f"(d[3])
        : "r"(a[0]), "r"(a[1]), "r"(a[2]), "r"(a[3]), "r"(b0), "r"(b1));
}

__device__ __forceinline__ void split2(float f0, float f1, uint32_t& hi, uint32_t& lo) {
    __nv_bfloat162 hh = __floats2bfloat162_rn(f0, f1);
    float r0 = f0 - __bfloat162float(hh.x);
    float r1 = f1 - __bfloat162float(hh.y);
    __nv_bfloat162 ll = __floats2bfloat162_rn(r0, r1);
    memcpy(&hi, &hh, 4);
    memcpy(&lo, &ll, 4);
}

#define SM_AHI  0
#define SM_ALO  16384
#define SM_BHI  32768
#define SM_BLO  65536
#define SM_TOT  98304

extern __shared__ char smc[];

// ---------------------------------------------------------------------------
// Weight precompute: 4 [128x128] fp32 -> swizzled bf16 hi/lo
// ---------------------------------------------------------------------------
__global__ void conv_w_kernel(const float* __restrict__ W0, const float* __restrict__ W1,
                              const float* __restrict__ W2, const float* __restrict__ W3)
{
    const int t = blockIdx.x * blockDim.x + threadIdx.x;
    if (t >= 8192) return;
    const int mat = t >> 11;
    const int rem = t & 2047;
    const int r = rem >> 4;
    const int c = rem & 15;
    const float* Wm = (mat == 0) ? W0 : (mat == 1) ? W1 : (mat == 2) ? W2 : W3;
    const float4 u = *(const float4*)(Wm + r * 128 + c * 8);
    const float4 v = *(const float4*)(Wm + r * 128 + c * 8 + 4);
    uint4 hi, lo;
    split2(u.x, u.y, hi.x, lo.x);
    split2(u.z, u.w, hi.y, lo.y);
    split2(v.x, v.y, hi.z, lo.z);
    split2(v.z, v.w, hi.w, lo.w);
    const int off = r * 16 + (c ^ (r & 7));
    g_wbf[mat][0][off] = hi;
    g_wbf[mat][1][off] = lo;
}

__device__ __forceinline__ void load_weights_smem(int wmat, int tid) {
    const uint4* whi = g_wbf[wmat][0];
    const uint4* wlo = g_wbf[wmat][1];
    uint4* shi = (uint4*)(smc + SM_BHI);
    uint4* slo = (uint4*)(smc + SM_BLO);
    #pragma unroll
    for (int it = 0; it < 8; it++) {
        const int i = tid + it * 256;
        shi[i] = whi[i];
        slo[i] = wlo[i];
    }
}

__device__ __forceinline__ void mma_mainloop(uint32_t sb, int tid, float acc[2][4][4]) {
    const int lane = tid & 31;
    const int wid  = tid >> 5;
    const int m0 = (wid & 1) * 32;
    const int n0 = (wid >> 1) * 32;
    const int sub = lane >> 3, l8 = lane & 7;
    for (int ks = 0; ks < 8; ks++) {
        uint32_t ahi[2][4], alo[2][4], bhi[2][4], blo[2][4];
        #pragma unroll
        for (int at = 0; at < 2; at++) {
            const int ar  = m0 + at * 16 + (sub & 1) * 8 + l8;
            const int akc = ks * 2 + (sub >> 1);
            const uint32_t aoff = (uint32_t)ar * 256u + (uint32_t)((akc ^ (ar & 7)) << 4);
            ldmx4(ahi[at], sb + SM_AHI + aoff);
            ldmx4(alo[at], sb + SM_ALO + aoff);
        }
        #pragma unroll
        for (int bp = 0; bp < 2; bp++) {
            const int br  = n0 + bp * 16 + (sub >> 1) * 8 + l8;
            const int bkc = ks * 2 + (sub & 1);
            const uint32_t boff = (uint32_t)br * 256u + (uint32_t)((bkc ^ (br & 7)) << 4);
            ldmx4(bhi[bp], sb + SM_BHI + boff);
            ldmx4(blo[bp], sb + SM_BLO + boff);
        }
        #pragma unroll
        for (int at = 0; at < 2; at++) {
            #pragma unroll
            for (int nt = 0; nt < 4; nt++) {
                const int bp = nt >> 1, o = (nt & 1) * 2;
                mma_bf16(acc[at][nt], ahi[at], bhi[bp][o], bhi[bp][o + 1]);
                mma_bf16(acc[at][nt], ahi[at], blo[bp][o], blo[bp][o + 1]);
                mma_bf16(acc[at][nt], alo[at], bhi[bp][o], bhi[bp][o + 1]);
            }
        }
    }
}

// ---------------------------------------------------------------------------
// HMMA GEMM: v = A@W^T + bias*deg (deg=1 if null);  out = mul ? mul*(1+v) : v
// 256 threads, 64-row tile, warps 2(m) x 4(n), 96KB smem -> 2 CTAs/SM.
// ---------------------------------------------------------------------------
__global__ void __launch_bounds__(256, 2)
gemm_hmma_kernel(const float* __restrict__ A, int wmat,
                 const float* __restrict__ bias, float* __restrict__ C, int M,
                 const int* __restrict__ deg, const float* __restrict__ mulSrc)
{
    const uint32_t sb = smem_u32(smc);
    const int tid = threadIdx.x;
    const int rowBase = blockIdx.x * 64;

    load_weights_smem(wmat, tid);

    // convert A tile (64 rows) to bf16 hi/lo swizzled smem
    #pragma unroll
    for (int it = 0; it < 4; it++) {
        const int task = tid + it * 256;     // 0..1023
        const int r = task >> 4;
        const int c = task & 15;
        const int grow = rowBase + r;
        float4 u = make_float4(0.f, 0.f, 0.f, 0.f), v = u;
        if (grow < M) {
            const float* Ar = A + (size_t)grow * D + c * 8;
            u = *(const float4*)Ar;
            v = *(const float4*)(Ar + 4);
        }
        uint4 hi, lo;
        split2(u.x, u.y, hi.x, lo.x);
        split2(u.z, u.w, hi.y, lo.y);
        split2(v.x, v.y, hi.z, lo.z);
        split2(v.z, v.w, hi.w, lo.w);
        const uint32_t off = (uint32_t)r * 256u + (uint32_t)((c ^ (r & 7)) << 4);
        *(uint4*)(smc + SM_AHI + off) = hi;
        *(uint4*)(smc + SM_ALO + off) = lo;
    }
    __syncthreads();

    float acc[2][4][4];
    #pragma unroll
    for (int at = 0; at < 2; at++)
        #pragma unroll
        for (int nt = 0; nt < 4; nt++)
            #pragma unroll
            for (int q = 0; q < 4; q++) acc[at][nt][q] = 0.f;

    mma_mainloop(sb, tid, acc);

    const int lane = tid & 31;
    const int wid  = tid >> 5;
    const int m0 = (wid & 1) * 32;
    const int n0 = (wid >> 1) * 32;
    const bool hasMul = (mulSrc != nullptr);
    #pragma unroll
    for (int at = 0; at < 2; at++) {
        const int rA = rowBase + m0 + at * 16 + (lane >> 2);
        const int rB = rA + 8;
        float dA = 1.f, dB = 1.f;
        if (deg != nullptr) {
            if (rA < M) dA = (float)deg[rA];
            if (rB < M) dB = (float)deg[rB];
        }
        #pragma unroll
        for (int nt = 0; nt < 4; nt++) {
            const int col = n0 + nt * 8 + (lane & 3) * 2;
            const float2 b2 = *(const float2*)(bias + col);
            if (rA < M) {
                float v0 = acc[at][nt][0] + b2.x * dA;
                float v1 = acc[at][nt][1] + b2.y * dA;
                if (hasMul) {
                    float2 m = *(const float2*)(mulSrc + (size_t)rA * D + col);
                    v0 = fmaf(m.x, v0, m.x);
                    v1 = fmaf(m.y, v1, m.y);
                }
                *(float2*)(C + (size_t)rA * D + col) = make_float2(v0, v1);
            }
            if (rB < M) {
                float v0 = acc[at][nt][2] + b2.x * dB;
                float v1 = acc[at][nt][3] + b2.y * dB;
                if (hasMul) {
                    float2 m = *(const float2*)(mulSrc + (size_t)rB * D + col);
                    v0 = fmaf(m.x, v0, m.x);
                    v1 = fmaf(m.y, v1, m.y);
                }
                *(float2*)(C + (size_t)rB * D + col) = make_float2(v0, v1);
            }
        }
    }
}

// ---------------------------------------------------------------------------
// CSR build (one direction per call)
// ---------------------------------------------------------------------------
__global__ void hist1_kernel(const int* __restrict__ idx, int* __restrict__ cnt, int E)
{
    int e = blockIdx.x * blockDim.x + threadIdx.x;
    if (e < E) atomicAdd(&cnt[idx[e]], 1);
}

__global__ void __launch_bounds__(1024)
offsets1_kernel(const int* __restrict__ cnt, int* __restrict__ beg,
                int* __restrict__ cur, int* __restrict__ ctr, int n)
{
    const int t = threadIdx.x;
    const int i = blockIdx.x * 1024 + t;
    int v = (i < n) ? cnt[i] : 0;

    const int lane = t & 31, wd = t >> 5;
    int s = v;
    #pragma unroll
    for (int o = 1; o < 32; o <<= 1) {
        int u = __shfl_up_sync(0xffffffffu, s, o);
        if (lane >= o) s += u;
    }
    __shared__ int wsum[32];
    __shared__ int base;
    if (lane == 31) wsum[wd] = s;
    __syncthreads();
    if (wd == 0) {
        int ws = wsum[lane];
        #pragma unroll
        for (int o = 1; o < 32; o <<= 1) {
            int u = __shfl_up_sync(0xffffffffu, ws, o);
            if (lane >= o) ws += u;
        }
        wsum[lane] = ws;
        if (lane == 31) base = atomicAdd(ctr, ws);
    }
    __syncthreads();
    int excl = base + s - v + (wd > 0 ? wsum[wd - 1] : 0);
    if (i < n) { beg[i] = excl; cur[i] = excl; }
}

__global__ void place1_kernel(const int* __restrict__ key, const int* __restrict__ val,
                              int* __restrict__ cur, int* __restrict__ dst, int E)
{
    int e = blockIdx.x * blockDim.x + threadIdx.x;
    if (e < E) {
        int p = atomicAdd(&cur[key[e]], 1);
        dst[p] = val[e];
    }
}

__global__ void zero_kernel(int* __restrict__ p, int n)
{
    int i = blockIdx.x * blockDim.x + threadIdx.x;
    if (i < n) p[i] = 0;
}

// ---------------------------------------------------------------------------
// Segment gather-reduce: warp per segment; predicated 8-wide MLP batches.
//   acc = sum_{k in [beg, beg+cnt)} src[lst[k]] ;  out = lin ? lin*(1+acc) : acc
// ---------------------------------------------------------------------------
__global__ void seg_reduce_kernel(const int* __restrict__ beg, const int* __restrict__ cnt,
                                  const int* __restrict__ lst,
                                  const float* __restrict__ src, const float* __restrict__ lin,
                                  float* __restrict__ out, int N)
{
    const int seg  = (blockIdx.x * blockDim.x + threadIdx.x) >> 5;
    const int lane = threadIdx.x & 31;
    if (seg >= N) return;
    int k = beg[seg];
    const int end = k + cnt[seg];
    const int j = lane * 4;
    float4 acc = make_float4(0.f, 0.f, 0.f, 0.f);

    for (; k + 8 <= end; k += 8) {
        int si[8];
        #pragma unroll
        for (int q = 0; q < 8; q++) si[q] = __ldg(&lst[k + q]);
        float4 v[8];
        #pragma unroll
        for (int q = 0; q < 8; q++)
            v[q] = *(const float4*)(src + (size_t)si[q] * D + j);
        #pragma unroll
        for (int q = 0; q < 8; q++) {
            acc.x += v[q].x; acc.y += v[q].y; acc.z += v[q].z; acc.w += v[q].w;
        }
    }
    if (k < end) {   // predicated batch tail (full MLP)
        int si[8];
        #pragma unroll
        for (int q = 0; q < 8; q++) {
            int kk = (k + q < end) ? (k + q) : (end - 1);
            si[q] = __ldg(&lst[kk]);
        }
        float4 v[8];
        #pragma unroll
        for (int q = 0; q < 8; q++)
            v[q] = *(const float4*)(src + (size_t)si[q] * D + j);
        #pragma unroll
        for (int q = 0; q < 8; q++) {
            if (k + q < end) {
                acc.x += v[q].x; acc.y += v[q].y; acc.z += v[q].z; acc.w += v[q].w;
            }
        }
    }

    float4 o;
    if (lin != nullptr) {
        float4 l = *(const float4*)(lin + (size_t)seg * D + j);
        o.x = fmaf(acc.x, l.x, l.x);
        o.y = fmaf(acc.y, l.y, l.y);
        o.z = fmaf(acc.z, l.z, l.z);
        o.w = fmaf(acc.w, l.w, l.w);
    } else {
        o = acc;
    }
    *(float4*)(out + (size_t)seg * D + j) = o;
}

extern "C" void kernel_launch(void* const* d_in, const int* in_sizes, int n_in,
                              void* d_out, int out_size)
{
    const float* x   = (const float*)d_in[0];
    const float* w   = (const float*)d_in[1];
    const float* Wx1 = (const float*)d_in[2];
    const float* bx1 = (const float*)d_in[3];
    const float* Ww1 = (const float*)d_in[4];
    const float* bw1 = (const float*)d_in[5];
    const float* Wx2 = (const float*)d_in[6];
    const float* bx2 = (const float*)d_in[7];
    const float* Ww2 = (const float*)d_in[8];
    const float* bw2 = (const float*)d_in[9];
    const int*   h   = (const int*)d_in[10];

    const int N_X = in_sizes[0] / D;
    const int N_W = in_sizes[1] / D;
    const int E   = in_sizes[10] / 2;
    const int* vidx = h;
    const int* eidx = h + E;

    float* out_w = (float*)d_out;
    float* out_x = (float*)d_out + (size_t)N_W * D;

    float *p_xv, *p_wv, *p_we, *p_s;
    int *p_cnt, *p_beg, *p_cur, *p_srcx, *p_srcw;
    cudaGetSymbolAddress((void**)&p_xv,   g_xv);
    cudaGetSymbolAddress((void**)&p_wv,   g_wv);
    cudaGetSymbolAddress((void**)&p_we,   g_we);
    cudaGetSymbolAddress((void**)&p_s,    g_s);
    cudaGetSymbolAddress((void**)&p_cnt,  g_cnt);
    cudaGetSymbolAddress((void**)&p_beg,  g_beg);
    cudaGetSymbolAddress((void**)&p_cur,  g_cur);
    cudaGetSymbolAddress((void**)&p_srcx, g_srcx);
    cudaGetSymbolAddress((void**)&p_srcw, g_srcw);
    int* p_ctr = p_cnt + N_X + N_W;   // 2 counters right after used region

    cudaFuncSetAttribute(gemm_hmma_kernel,
                         cudaFuncAttributeMaxDynamicSharedMemorySize, SM_TOT);

    static cudaStream_t sA = nullptr, sB = nullptr, sC = nullptr;
    static cudaEvent_t e0, eBx, eBw, eA, eCv, eC, eS1;
    if (sA == nullptr) {
        cudaStreamCreateWithFlags(&sA, cudaStreamNonBlocking);
        cudaStreamCreateWithFlags(&sB, cudaStreamNonBlocking);
        cudaStreamCreateWithFlags(&sC, cudaStreamNonBlocking);
        cudaEventCreateWithFlags(&e0,  cudaEventDisableTiming);
        cudaEventCreateWithFlags(&eBx, cudaEventDisableTiming);
        cudaEventCreateWithFlags(&eBw, cudaEventDisableTiming);
        cudaEventCreateWithFlags(&eA,  cudaEventDisableTiming);
        cudaEventCreateWithFlags(&eCv, cudaEventDisableTiming);
        cudaEventCreateWithFlags(&eC,  cudaEventDisableTiming);
        cudaEventCreateWithFlags(&eS1, cudaEventDisableTiming);
    }

    const int gx  = (N_X + 63) / 64;
    const int gw  = (N_W + 63) / 64;
    const int nbx = (N_X + 1023) / 1024;
    const int nbw = (N_W + 1023) / 1024;
    const int ge  = (E + 255) / 256;

    // fork
    cudaEventRecord(e0, 0);
    cudaStreamWaitEvent(sA, e0, 0);
    cudaStreamWaitEvent(sB, e0, 0);
    cudaStreamWaitEvent(sC, e0, 0);

    // ---- stream B: CSR-x (launches 1-3) ----
    hist1_kernel<<<ge, 256, 0, sB>>>(vidx, p_cnt, E);
    offsets1_kernel<<<nbx, 1024, 0, sB>>>(p_cnt, p_beg, p_cur, p_ctr, N_X);
    place1_kernel<<<ge, 256, 0, sB>>>(vidx, eidx, p_cur, p_srcx, E);
    cudaEventRecord(eBx, sB);

    // ---- stream A: conv_w + wv + xv GEMMs (launches 4-6; #6 = big xv GEMM) ----
    conv_w_kernel<<<32, 256, 0, sA>>>(Ww1, Wx1, Ww2, Wx2);
    cudaEventRecord(eCv, sA);
    gemm_hmma_kernel<<<gw, 256, SM_TOT, sA>>>(w, 0, bw1, p_wv, N_W, nullptr, nullptr);
    gemm_hmma_kernel<<<gx, 256, SM_TOT, sA>>>(x, 1, bx1, p_xv, N_X, nullptr, nullptr);
    cudaEventRecord(eA, sA);

    // ---- sr1: out_x = xv*(1 + segsum_v(wv)) ----
    cudaStreamWaitEvent(0, eBx, 0);
    cudaStreamWaitEvent(0, eA, 0);
    seg_reduce_kernel<<<(N_X + 7) / 8, 256>>>(p_beg, p_cnt, p_srcx, p_wv, p_xv, out_x, N_X);
    cudaEventRecord(eS1, 0);

    // ---- stream C: we GEMM (needs only conv_w; overlaps everything) ----
    cudaStreamWaitEvent(sC, eCv, 0);
    gemm_hmma_kernel<<<gw, 256, SM_TOT, sC>>>(w, 2, bw2, p_we, N_W, nullptr, nullptr);
    cudaEventRecord(eC, sC);

    // ---- stream B: CSR-w (overlaps GEMMs + sr1) ----
    hist1_kernel<<<ge, 256, 0, sB>>>(eidx, p_cnt + N_X, E);
    offsets1_kernel<<<nbw, 1024, 0, sB>>>(p_cnt + N_X, p_beg + N_X, p_cur + N_X,
                                          p_ctr + 1, N_W);
    place1_kernel<<<ge, 256, 0, sB>>>(eidx, vidx, p_cur + N_X, p_srcw, E);
    cudaEventRecord(eBw, sB);

    // ---- sr2: s = segsum_e(out_x) ----
    cudaStreamWaitEvent(0, eBw, 0);
    seg_reduce_kernel<<<(N_W + 7) / 8, 256>>>(p_beg + N_X, p_cnt + N_X, p_srcw,
                                              out_x, nullptr, p_s, N_W);

    // ---- final: w_new = we*(1 + s@Wx2^T + deg_w*bx2) ----
    cudaStreamWaitEvent(0, eC, 0);
    gemm_hmma_kernel<<<gw, 256, SM_TOT>>>(p_s, 3, bx2, out_w, N_W, p_cnt + N_X, p_we);

    // ---- tail: restore zero-invariant ----
    zero_kernel<<<(N_X + N_W + 2 + 255) / 256, 256>>>(p_cnt, N_X + N_W + 2);
}